// round 4
// baseline (speedup 1.0000x reference)
#include <cuda_runtime.h>

#define T_DIM 2048
#define NI    4096
#define L     32
#define F     16
#define NROWS 72          // staged rows: t0-65 .. t0+6

typedef unsigned long long ull;

__device__ float g_wn[L * F];

__device__ __forceinline__ ull ffma2(ull a, ull b, ull c) {
    ull d;
    asm("fma.rn.f32x2 %0, %1, %2, %3;" : "=l"(d) : "l"(a), "l"(b), "l"(c));
    return d;
}

__device__ __forceinline__ ull pack2(float x) {
    ull d;
    asm("mov.b64 %0, {%1, %1};" : "=l"(d) : "f"(x));
    return d;
}

// pos-constraint + L2-normalize weights over lag axis
__global__ void prep_kernel(const float* __restrict__ w) {
    int f = threadIdx.x;
    if (f < F) {
        float col[L];
        float s = 0.f;
#pragma unroll
        for (int j = 0; j < L; j++) {
            float v = fmaxf(w[j * F + f], 0.f);
            col[j] = v;
            s += v * v;
        }
        float inv = rsqrtf(fmaxf(s, 1e-12f));
#pragma unroll
        for (int j = 0; j < L; j++) g_wn[j * F + f] = col[j] * inv;
    }
}

// 512-thread block = 128 i-lanes x 2 filter-halves x 2 t-groups.
// Each thread: 4 consecutive t, 8 filters -> 16 acc pairs (32 regs).
// Target 2 CTAs/SM -> 32 warps/SM for issue-rate saturation.
__global__ __launch_bounds__(512, 2) void conv_kernel(const float* __restrict__ x,
                                                      const float* __restrict__ bias,
                                                      float* __restrict__ out) {
    __shared__ float sx[NROWS * 128];   // 36 KB x window
    __shared__ ull   sw[L * F / 2];     // 2 KB packed weights
    __shared__ ull   sb[F / 2];

    const int tid  = threadIdx.x;
    const int lane = tid & 127;
    const int fh   = (tid >> 7) & 1;
    const int tg   = tid >> 8;          // 0/1: which 4-t group
    const int t0   = blockIdx.y * 8;
    const int ib   = blockIdx.x * 128;

    // ---- stage x window via cp.async (zero-fill t<0 rows) ----
    {
        unsigned sx_u = (unsigned)__cvta_generic_to_shared(sx);
#pragma unroll
        for (int k = 0; k < 5; k++) {
            int c = tid + k * 512;               // 16B chunks, 2304 total
            if (c < NROWS * 32) {
                int row = c >> 5;
                int col = (c & 31) * 4;
                int g   = t0 - 65 + row;
                unsigned dst = sx_u + (unsigned)(row * 128 + col) * 4u;
                const float* src = x + (long)max(g, 0) * NI + ib + col;
                int sz = (g >= 0) ? 16 : 0;
                asm volatile("cp.async.cg.shared.global [%0], [%1], 16, %2;"
                             :: "r"(dst), "l"(src), "r"(sz));
            }
        }
        asm volatile("cp.async.commit_group;");
    }

    if (tid < 256)    sw[tid] = reinterpret_cast<const ull*>(g_wn)[tid];
    if (tid < F / 2)  sb[tid] = reinterpret_cast<const ull*>(bias)[tid];

    asm volatile("cp.async.wait_group 0;");
    __syncthreads();

    // ---- compute ----
    ull acc[4][4];
#pragma unroll
    for (int r = 0; r < 4; r++)
#pragma unroll
        for (int p = 0; p < 4; p++) acc[r][p] = sb[fh * 4 + p];

    const float* sxf = sx + lane;
    const int base = 64 + tg * 4;       // smem row of x[tb-1]

    // window: xw[r] = x[tb-1+r], tb = t0 + tg*4
    float xw[4];
#pragma unroll
    for (int r = 0; r < 4; r++) xw[r] = sxf[(base + r) * 128];

#pragma unroll
    for (int j = 0; j < L; j++) {
        ull w[4];
#pragma unroll
        for (int p = 0; p < 4; p++) w[p] = sw[j * 8 + fh * 4 + p];

        // fresh x pair for next lag (rows tb-3-2j, tb-2-2j)
        float n0 = 0.f, n1 = 0.f;
        if (j < L - 1) {
            n0 = sxf[(base - 2 - 2 * j) * 128];
            n1 = sxf[(base - 1 - 2 * j) * 128];
        }

#pragma unroll
        for (int r = 0; r < 4; r++) {
            ull xp = pack2(xw[r]);
#pragma unroll
            for (int p = 0; p < 4; p++) acc[r][p] = ffma2(xp, w[p], acc[r][p]);
        }

        xw[3] = xw[1];
        xw[2] = xw[0];
        xw[1] = n1;
        xw[0] = n0;
    }

    // ---- ReLU + vectorized store ----
    const int tb = t0 + tg * 4;
#pragma unroll
    for (int r = 0; r < 4; r++) {
        float4 v[2];
        float* vf = reinterpret_cast<float*>(v);
        const float* af = reinterpret_cast<const float*>(acc[r]);
#pragma unroll
        for (int k = 0; k < 8; k++) vf[k] = fmaxf(af[k], 0.f);
        float4* o = reinterpret_cast<float4*>(out + (long)(tb + r) * (NI * F)
                                              + (ib + lane) * F + fh * 8);
        o[0] = v[0];
        o[1] = v[1];
    }
}

extern "C" void kernel_launch(void* const* d_in, const int* in_sizes, int n_in,
                              void* d_out, int out_size) {
    const float* x    = (const float*)d_in[0];
    const float* w    = (const float*)d_in[1];
    const float* bias = (const float*)d_in[2];
    float* out        = (float*)d_out;

    prep_kernel<<<1, 32>>>(w);

    dim3 grid(NI / 128, T_DIM / 8);
    conv_kernel<<<grid, 512>>>(x, bias, out);
}

// round 6
// speedup vs baseline: 1.6922x; 1.6922x over previous
#include <cuda_runtime.h>
#include <cstdint>

#define T_DIM 2048
#define NI    4096
#define L     32
#define F     16
#define TCH   128             // t per CTA
#define WINR  (TCH + 62)      // 190 staged rows per channel
#define XSTR  193             // smem row stride (odd -> conflict-free)

__device__ float g_wh[L * F];  // [k][f], lag-reversed+normalized, tf32-rounded
__device__ float g_wl[L * F];  // residual

__device__ __forceinline__ float tf32r(float x) {
    uint32_t u;
    asm("cvt.rna.tf32.f32 %0, %1;" : "=r"(u) : "f"(x));
    return __uint_as_float(u);
}

#define MMA(c0,c1,c2,c3,a0,a1,a2,a3,b0,b1)                              \
    asm("mma.sync.aligned.m16n8k8.row.col.f32.tf32.tf32.f32 "           \
        "{%0,%1,%2,%3}, {%4,%5,%6,%7}, {%8,%9}, {%0,%1,%2,%3};"         \
        : "+f"(c0), "+f"(c1), "+f"(c2), "+f"(c3)                        \
        : "r"(a0), "r"(a1), "r"(a2), "r"(a3), "r"(b0), "r"(b1))

// pos-constraint + l2-normalize + lag-reverse + tf32 hi/lo split
__global__ void prep_kernel(const float* __restrict__ w) {
    int f = threadIdx.x;
    if (f < F) {
        float col[L];
        float s = 0.f;
#pragma unroll
        for (int j = 0; j < L; j++) {
            float v = fmaxf(w[j * F + f], 0.f);
            col[j] = v;
            s += v * v;
        }
        float inv = rsqrtf(fmaxf(s, 1e-12f));
#pragma unroll
        for (int k = 0; k < L; k++) {
            float v  = col[L - 1 - k] * inv;    // W[k][f] = w_pn[31-k][f]
            float vh = tf32r(v);
            g_wh[k * F + f] = vh;
            g_wl[k * F + f] = v - vh;
        }
    }
}

// CTA: 8 warps, warp w owns channel i = ib + w, computes out[t0..t0+127, i, 0..15].
// Per warp: 8 m-tiles (16 t each) x 4 k-steps x (2 n-tiles x 3 split-terms) mma.
__global__ __launch_bounds__(256, 2) void conv_kernel(const float* __restrict__ x,
                                                      const float* __restrict__ bias,
                                                      float* __restrict__ out) {
    __shared__ float sxh[8 * XSTR];
    __shared__ float sxl[8 * XSTR];

    const int tid  = threadIdx.x;
    const int w    = tid >> 5;
    const int lane = tid & 31;
    const int g    = lane >> 2;      // groupID
    const int tg   = lane & 3;       // threadID_in_group
    const int ib   = blockIdx.x * 8;
    const int t0   = blockIdx.y * TCH;

    // ---- stage x window transposed + tf32-split: sxh[i_loc][t_loc] ----
#pragma unroll
    for (int p = 0; p < 6; p++) {
        int idx = tid + p * 256;           // 1536 = 8 ch x 192 rows
        int row = idx >> 3;
        int il  = idx & 7;
        int tau = t0 - 63 + row;
        float v = 0.f;
        if (row < WINR && tau >= 0) v = x[(long)tau * NI + ib + il];
        float h = tf32r(v);
        sxh[il * XSTR + row] = h;
        sxl[il * XSTR + row] = v - h;
    }

    // ---- B fragments (held in regs for whole kernel) ----
    // b0 = B[tg][g+nb], b1 = B[tg+4][g+nb], k = s*8 + (tg | tg+4)
    uint32_t bh[4][2][2], bl[4][2][2];
#pragma unroll
    for (int s = 0; s < 4; s++) {
        int k0 = s * 8 + tg;
#pragma unroll
        for (int n = 0; n < 2; n++) {
            int fc = n * 8 + g;
            bh[s][n][0] = __float_as_uint(g_wh[k0 * F + fc]);
            bh[s][n][1] = __float_as_uint(g_wh[(k0 + 4) * F + fc]);
            bl[s][n][0] = __float_as_uint(g_wl[k0 * F + fc]);
            bl[s][n][1] = __float_as_uint(g_wl[(k0 + 4) * F + fc]);
        }
    }

    const float2 bias0 = *reinterpret_cast<const float2*>(bias + 2 * tg);
    const float2 bias1 = *reinterpret_cast<const float2*>(bias + 8 + 2 * tg);

    __syncthreads();

    // rolling A window: W[j] = x-window value at t_loc = mt*16 + (g+2tg) + 8j
    const float* ph = sxh + w * XSTR + g + 2 * tg;
    const float* pl = sxl + w * XSTR + g + 2 * tg;
    float Wh[9], Wl[9];
#pragma unroll
    for (int j = 0; j < 9; j++) { Wh[j] = ph[8 * j]; Wl[j] = pl[8 * j]; }

    const long obase = (long)(ib + w) * F;

#pragma unroll
    for (int mt = 0; mt < 8; mt++) {
        float c00 = 0.f, c01 = 0.f, c02 = 0.f, c03 = 0.f;
        float c10 = 0.f, c11 = 0.f, c12 = 0.f, c13 = 0.f;

#pragma unroll
        for (int s = 0; s < 4; s++) {
            // Toeplitz: a1 == a2 (A[g+8][k] == A[g][k+4])
            uint32_t ah0 = __float_as_uint(Wh[2 * s]);
            uint32_t ah1 = __float_as_uint(Wh[2 * s + 1]);
            uint32_t ah3 = __float_as_uint(Wh[2 * s + 2]);
            uint32_t al0 = __float_as_uint(Wl[2 * s]);
            uint32_t al1 = __float_as_uint(Wl[2 * s + 1]);
            uint32_t al3 = __float_as_uint(Wl[2 * s + 2]);

            MMA(c00, c01, c02, c03, ah0, ah1, ah1, ah3, bh[s][0][0], bh[s][0][1]);
            MMA(c10, c11, c12, c13, ah0, ah1, ah1, ah3, bh[s][1][0], bh[s][1][1]);
            MMA(c00, c01, c02, c03, ah0, ah1, ah1, ah3, bl[s][0][0], bl[s][0][1]);
            MMA(c10, c11, c12, c13, ah0, ah1, ah1, ah3, bl[s][1][0], bl[s][1][1]);
            MMA(c00, c01, c02, c03, al0, al1, al1, al3, bh[s][0][0], bh[s][0][1]);
            MMA(c10, c11, c12, c13, al0, al1, al1, al3, bh[s][1][0], bh[s][1][1]);
        }

        // epilogue: bias + relu + store.  c0/c1 -> row g, c2/c3 -> row g+8
        {
            int ta = t0 + mt * 16 + g;
            float2 v;
            v.x = fmaxf(c00 + bias0.x, 0.f);
            v.y = fmaxf(c01 + bias0.y, 0.f);
            *reinterpret_cast<float2*>(out + (long)ta * (NI * F) + obase + 2 * tg) = v;
            v.x = fmaxf(c10 + bias1.x, 0.f);
            v.y = fmaxf(c11 + bias1.y, 0.f);
            *reinterpret_cast<float2*>(out + (long)ta * (NI * F) + obase + 8 + 2 * tg) = v;
            int tb = ta + 8;
            v.x = fmaxf(c02 + bias0.x, 0.f);
            v.y = fmaxf(c03 + bias0.y, 0.f);
            *reinterpret_cast<float2*>(out + (long)tb * (NI * F) + obase + 2 * tg) = v;
            v.x = fmaxf(c12 + bias1.x, 0.f);
            v.y = fmaxf(c13 + bias1.y, 0.f);
            *reinterpret_cast<float2*>(out + (long)tb * (NI * F) + obase + 8 + 2 * tg) = v;
        }

        // roll window forward by one m-tile (16 t = 2 positions of 8)
        if (mt < 7) {
#pragma unroll
            for (int j = 0; j < 7; j++) { Wh[j] = Wh[j + 2]; Wl[j] = Wl[j + 2]; }
            Wh[7] = ph[(mt + 1) * 16 + 56];
            Wl[7] = pl[(mt + 1) * 16 + 56];
            Wh[8] = ph[(mt + 1) * 16 + 64];
            Wl[8] = pl[(mt + 1) * 16 + 64];
        }
    }
}

extern "C" void kernel_launch(void* const* d_in, const int* in_sizes, int n_in,
                              void* d_out, int out_size) {
    const float* x    = (const float*)d_in[0];
    const float* w    = (const float*)d_in[1];
    const float* bias = (const float*)d_in[2];
    float* out        = (float*)d_out;

    prep_kernel<<<1, 32>>>(w);

    dim3 grid(NI / 8, T_DIM / TCH);
    conv_kernel<<<grid, 256>>>(x, bias, out);
}

// round 7
// speedup vs baseline: 1.7787x; 1.0512x over previous
#include <cuda_runtime.h>
#include <cstdint>

#define T_DIM 2048
#define NI    4096
#define L     32
#define F     16
#define TCH   128             // t per CTA
#define WINR  (TCH + 62)      // 190 staged rows per channel
#define XSTR  193             // smem row stride (odd -> conflict-free)

__device__ float g_wh[L * F];  // [k][f], lag-reversed+normalized, tf32-rounded
__device__ float g_wl[L * F];  // residual

__device__ __forceinline__ float tf32r(float x) {
    uint32_t u;
    asm("cvt.rna.tf32.f32 %0, %1;" : "=r"(u) : "f"(x));
    return __uint_as_float(u);
}

#define MMA(c0,c1,c2,c3,a0,a1,a2,a3,b0,b1)                              \
    asm("mma.sync.aligned.m16n8k8.row.col.f32.tf32.tf32.f32 "           \
        "{%0,%1,%2,%3}, {%4,%5,%6,%7}, {%8,%9}, {%0,%1,%2,%3};"         \
        : "+f"(c0), "+f"(c1), "+f"(c2), "+f"(c3)                        \
        : "r"(a0), "r"(a1), "r"(a2), "r"(a3), "r"(b0), "r"(b1))

// pos-constraint + l2-normalize + lag-reverse + tf32 hi/lo split
__global__ void prep_kernel(const float* __restrict__ w) {
    int f = threadIdx.x;
    if (f < F) {
        float col[L];
        float s = 0.f;
#pragma unroll
        for (int j = 0; j < L; j++) {
            float v = fmaxf(w[j * F + f], 0.f);
            col[j] = v;
            s += v * v;
        }
        float inv = rsqrtf(fmaxf(s, 1e-12f));
#pragma unroll
        for (int k = 0; k < L; k++) {
            float v  = col[L - 1 - k] * inv;    // W[k][f] = w_pn[31-k][f]
            float vh = tf32r(v);
            g_wh[k * F + f] = vh;
            g_wl[k * F + f] = v - vh;
        }
    }
}

// CTA: 8 warps, warp w owns channel i = ib + w, computes out[t0..t0+127, i, :].
// B columns permuted so each lane's 4 C-values per row are filters 4tg..4tg+3
// (one contiguous STG.128 per row instead of scattered STG.64s).
__global__ __launch_bounds__(256, 2) void conv_kernel(const float* __restrict__ x,
                                                      const float* __restrict__ bias,
                                                      float* __restrict__ out) {
    __shared__ float sxh[8 * XSTR];
    __shared__ float sxl[8 * XSTR];

    const int tid  = threadIdx.x;
    const int w    = tid >> 5;
    const int lane = tid & 31;
    const int g    = lane >> 2;      // groupID
    const int tg   = lane & 3;       // threadID_in_group
    const int ib   = blockIdx.x * 8;
    const int t0   = blockIdx.y * TCH;

    // ---- stage x window transposed + tf32-split: sxh[i_loc][t_loc] ----
#pragma unroll
    for (int p = 0; p < 6; p++) {
        int idx = tid + p * 256;           // 1536 = 8 ch x 192 rows
        int row = idx >> 3;
        int il  = idx & 7;
        int tau = t0 - 63 + row;
        float v = 0.f;
        if (row < WINR && tau >= 0) v = x[(long)tau * NI + ib + il];
        float h = tf32r(v);
        sxh[il * XSTR + row] = h;
        sxl[il * XSTR + row] = v - h;
    }

    // ---- B fragments with permuted filter columns ----
    // ntile0 col c -> f = (c even) ? 2c : 2c-1 ; ntile1 col c -> (c even) ? 2c+2 : 2c+1
    const int fc0 = (g & 1) ? (2 * g - 1) : (2 * g);
    const int fc1 = (g & 1) ? (2 * g + 1) : (2 * g + 2);
    uint32_t bh[4][2][2], bl[4][2][2];
#pragma unroll
    for (int s = 0; s < 4; s++) {
        int k0 = s * 8 + tg;
        bh[s][0][0] = __float_as_uint(g_wh[k0 * F + fc0]);
        bh[s][0][1] = __float_as_uint(g_wh[(k0 + 4) * F + fc0]);
        bl[s][0][0] = __float_as_uint(g_wl[k0 * F + fc0]);
        bl[s][0][1] = __float_as_uint(g_wl[(k0 + 4) * F + fc0]);
        bh[s][1][0] = __float_as_uint(g_wh[k0 * F + fc1]);
        bh[s][1][1] = __float_as_uint(g_wh[(k0 + 4) * F + fc1]);
        bl[s][1][0] = __float_as_uint(g_wl[k0 * F + fc1]);
        bl[s][1][1] = __float_as_uint(g_wl[(k0 + 4) * F + fc1]);
    }

    // bias quad for this lane's filters 4tg..4tg+3
    const float4 bq = reinterpret_cast<const float4*>(bias)[tg];

    __syncthreads();

    // rolling A window: W[j] = x-window value at t_loc = mt*16 + (g+2tg) + 8j
    const float* ph = sxh + w * XSTR + g + 2 * tg;
    const float* pl = sxl + w * XSTR + g + 2 * tg;
    float Wh[9], Wl[9];
#pragma unroll
    for (int j = 0; j < 9; j++) { Wh[j] = ph[8 * j]; Wl[j] = pl[8 * j]; }

    float* const obase = out + (long)(ib + w) * F + 4 * tg;

#pragma unroll
    for (int mt = 0; mt < 8; mt++) {
        float c00 = 0.f, c01 = 0.f, c02 = 0.f, c03 = 0.f;
        float c10 = 0.f, c11 = 0.f, c12 = 0.f, c13 = 0.f;

#pragma unroll
        for (int s = 0; s < 4; s++) {
            // Toeplitz: a1 == a2 (A[g+8][k] == A[g][k+4])
            uint32_t ah0 = __float_as_uint(Wh[2 * s]);
            uint32_t ah1 = __float_as_uint(Wh[2 * s + 1]);
            uint32_t ah3 = __float_as_uint(Wh[2 * s + 2]);
            uint32_t al0 = __float_as_uint(Wl[2 * s]);
            uint32_t al1 = __float_as_uint(Wl[2 * s + 1]);
            uint32_t al3 = __float_as_uint(Wl[2 * s + 2]);

            MMA(c00, c01, c02, c03, ah0, ah1, ah1, ah3, bh[s][0][0], bh[s][0][1]);
            MMA(c10, c11, c12, c13, ah0, ah1, ah1, ah3, bh[s][1][0], bh[s][1][1]);
            MMA(c00, c01, c02, c03, ah0, ah1, ah1, ah3, bl[s][0][0], bl[s][0][1]);
            MMA(c10, c11, c12, c13, ah0, ah1, ah1, ah3, bl[s][1][0], bl[s][1][1]);
            MMA(c00, c01, c02, c03, al0, al1, al1, al3, bh[s][0][0], bh[s][0][1]);
            MMA(c10, c11, c12, c13, al0, al1, al1, al3, bh[s][1][0], bh[s][1][1]);
        }

        // epilogue: bias + relu, one STG.128 per row
        {
            int ta = t0 + mt * 16 + g;
            float4 va;
            va.x = fmaxf(c00 + bq.x, 0.f);
            va.y = fmaxf(c01 + bq.y, 0.f);
            va.z = fmaxf(c10 + bq.z, 0.f);
            va.w = fmaxf(c11 + bq.w, 0.f);
            *reinterpret_cast<float4*>(obase + (long)ta * (NI * F)) = va;
            float4 vb;
            vb.x = fmaxf(c02 + bq.x, 0.f);
            vb.y = fmaxf(c03 + bq.y, 0.f);
            vb.z = fmaxf(c12 + bq.z, 0.f);
            vb.w = fmaxf(c13 + bq.w, 0.f);
            *reinterpret_cast<float4*>(obase + (long)(ta + 8) * (NI * F)) = vb;
        }

        // roll window forward by one m-tile (16 t = 2 positions of 8)
        if (mt < 7) {
#pragma unroll
            for (int j = 0; j < 7; j++) { Wh[j] = Wh[j + 2]; Wl[j] = Wl[j + 2]; }
            Wh[7] = ph[(mt + 1) * 16 + 56];
            Wl[7] = pl[(mt + 1) * 16 + 56];
            Wh[8] = ph[(mt + 1) * 16 + 64];
            Wl[8] = pl[(mt + 1) * 16 + 64];
        }
    }
}

extern "C" void kernel_launch(void* const* d_in, const int* in_sizes, int n_in,
                              void* d_out, int out_size) {
    const float* x    = (const float*)d_in[0];
    const float* w    = (const float*)d_in[1];
    const float* bias = (const float*)d_in[2];
    float* out        = (float*)d_out;

    prep_kernel<<<1, 32>>>(w);

    dim3 grid(NI / 8, T_DIM / TCH);
    conv_kernel<<<grid, 256>>>(x, bias, out);
}

// round 8
// speedup vs baseline: 2.0107x; 1.1304x over previous
#include <cuda_runtime.h>
#include <cstdint>

#define T_DIM 2048
#define NI    4096
#define L     32
#define F     16
#define TCH   128             // t per CTA
#define WINR  (TCH + 62)      // 190 staged rows per channel
#define XSTR  193             // smem row stride (odd -> conflict-free)

__device__ float g_wh[L * F];  // [k][f], lag-reversed+normalized, tf32-rounded

__device__ __forceinline__ float tf32r(float x) {
    uint32_t u;
    asm("cvt.rna.tf32.f32 %0, %1;" : "=r"(u) : "f"(x));
    return __uint_as_float(u);
}

#define MMA(c0,c1,c2,c3,a0,a1,a2,a3,b0,b1)                              \
    asm("mma.sync.aligned.m16n8k8.row.col.f32.tf32.tf32.f32 "           \
        "{%0,%1,%2,%3}, {%4,%5,%6,%7}, {%8,%9}, {%0,%1,%2,%3};"         \
        : "+f"(c0), "+f"(c1), "+f"(c2), "+f"(c3)                        \
        : "r"(a0), "r"(a1), "r"(a2), "r"(a3), "r"(b0), "r"(b1))

// pos-constraint + l2-normalize + lag-reverse + tf32 round
__global__ void prep_kernel(const float* __restrict__ w) {
    int f = threadIdx.x;
    if (f < F) {
        float col[L];
        float s = 0.f;
#pragma unroll
        for (int j = 0; j < L; j++) {
            float v = fmaxf(w[j * F + f], 0.f);
            col[j] = v;
            s += v * v;
        }
        float inv = rsqrtf(fmaxf(s, 1e-12f));
#pragma unroll
        for (int k = 0; k < L; k++)
            g_wh[k * F + f] = tf32r(col[L - 1 - k] * inv);  // W[k][f] = w_pn[31-k][f]
    }
}

// CTA: 8 warps, warp w owns channel i = ib + w, computes out[t0..t0+127, i, :].
// 2-term split: (Ah + Al) x Bh with independent accumulator sets for max ILP.
// B columns permuted so each lane's 4 C-values per row are contiguous filters.
__global__ __launch_bounds__(256, 2) void conv_kernel(const float* __restrict__ x,
                                                      const float* __restrict__ bias,
                                                      float* __restrict__ out) {
    __shared__ float sxh[8 * XSTR];
    __shared__ float sxl[8 * XSTR];

    const int tid  = threadIdx.x;
    const int w    = tid >> 5;
    const int lane = tid & 31;
    const int g    = lane >> 2;      // groupID
    const int tg   = lane & 3;       // threadID_in_group
    const int ib   = blockIdx.x * 8;
    const int t0   = blockIdx.y * TCH;

    // ---- stage x window transposed + tf32-split: sxh[i_loc][t_loc] ----
#pragma unroll
    for (int p = 0; p < 6; p++) {
        int idx = tid + p * 256;           // 1536 = 8 ch x 192 rows
        int row = idx >> 3;
        int il  = idx & 7;
        int tau = t0 - 63 + row;
        float v = 0.f;
        if (row < WINR && tau >= 0) v = x[(long)tau * NI + ib + il];
        float h = tf32r(v);
        sxh[il * XSTR + row] = h;
        sxl[il * XSTR + row] = v - h;
    }

    // ---- B fragments with permuted filter columns ----
    // ntile0 col c -> f = (c even) ? 2c : 2c-1 ; ntile1 col c -> (c even) ? 2c+2 : 2c+1
    const int fc0 = (g & 1) ? (2 * g - 1) : (2 * g);
    const int fc1 = (g & 1) ? (2 * g + 1) : (2 * g + 2);
    uint32_t bh[4][2][2];
#pragma unroll
    for (int s = 0; s < 4; s++) {
        int k0 = s * 8 + tg;
        bh[s][0][0] = __float_as_uint(g_wh[k0 * F + fc0]);
        bh[s][0][1] = __float_as_uint(g_wh[(k0 + 4) * F + fc0]);
        bh[s][1][0] = __float_as_uint(g_wh[k0 * F + fc1]);
        bh[s][1][1] = __float_as_uint(g_wh[(k0 + 4) * F + fc1]);
    }

    // bias quad for this lane's filters 4tg..4tg+3
    const float4 bq = reinterpret_cast<const float4*>(bias)[tg];

    __syncthreads();

    // rolling A window: W[j] = x-window value at t_loc = mt*16 + (g+2tg) + 8j
    const float* ph = sxh + w * XSTR + g + 2 * tg;
    const float* pl = sxl + w * XSTR + g + 2 * tg;
    float Wh[9], Wl[9];
#pragma unroll
    for (int j = 0; j < 9; j++) { Wh[j] = ph[8 * j]; Wl[j] = pl[8 * j]; }

    float* const obase = out + (long)(ib + w) * F + 4 * tg;

#pragma unroll
    for (int mt = 0; mt < 8; mt++) {
        // independent accumulator sets: h-term and l-term, 2 n-tiles each
        float h00 = 0.f, h01 = 0.f, h02 = 0.f, h03 = 0.f;
        float h10 = 0.f, h11 = 0.f, h12 = 0.f, h13 = 0.f;
        float l00 = 0.f, l01 = 0.f, l02 = 0.f, l03 = 0.f;
        float l10 = 0.f, l11 = 0.f, l12 = 0.f, l13 = 0.f;

#pragma unroll
        for (int s = 0; s < 4; s++) {
            // Toeplitz: a1 == a2 (A[g+8][k] == A[g][k+4])
            uint32_t ah0 = __float_as_uint(Wh[2 * s]);
            uint32_t ah1 = __float_as_uint(Wh[2 * s + 1]);
            uint32_t ah3 = __float_as_uint(Wh[2 * s + 2]);
            uint32_t al0 = __float_as_uint(Wl[2 * s]);
            uint32_t al1 = __float_as_uint(Wl[2 * s + 1]);
            uint32_t al3 = __float_as_uint(Wl[2 * s + 2]);

            MMA(h00, h01, h02, h03, ah0, ah1, ah1, ah3, bh[s][0][0], bh[s][0][1]);
            MMA(h10, h11, h12, h13, ah0, ah1, ah1, ah3, bh[s][1][0], bh[s][1][1]);
            MMA(l00, l01, l02, l03, al0, al1, al1, al3, bh[s][0][0], bh[s][0][1]);
            MMA(l10, l11, l12, l13, al0, al1, al1, al3, bh[s][1][0], bh[s][1][1]);
        }

        // epilogue: combine terms + bias + relu, one STG.128 per row
        {
            int ta = t0 + mt * 16 + g;
            float4 va;
            va.x = fmaxf(h00 + l00 + bq.x, 0.f);
            va.y = fmaxf(h01 + l01 + bq.y, 0.f);
            va.z = fmaxf(h10 + l10 + bq.z, 0.f);
            va.w = fmaxf(h11 + l11 + bq.w, 0.f);
            *reinterpret_cast<float4*>(obase + (long)ta * (NI * F)) = va;
            float4 vb;
            vb.x = fmaxf(h02 + l02 + bq.x, 0.f);
            vb.y = fmaxf(h03 + l03 + bq.y, 0.f);
            vb.z = fmaxf(h12 + l12 + bq.z, 0.f);
            vb.w = fmaxf(h13 + l13 + bq.w, 0.f);
            *reinterpret_cast<float4*>(obase + (long)(ta + 8) * (NI * F)) = vb;
        }

        // roll window forward by one m-tile (16 t = 2 positions of 8)
        if (mt < 7) {
#pragma unroll
            for (int j = 0; j < 7; j++) { Wh[j] = Wh[j + 2]; Wl[j] = Wl[j + 2]; }
            Wh[7] = ph[(mt + 1) * 16 + 56];
            Wl[7] = pl[(mt + 1) * 16 + 56];
            Wh[8] = ph[(mt + 1) * 16 + 64];
            Wl[8] = pl[(mt + 1) * 16 + 64];
        }
    }
}

extern "C" void kernel_launch(void* const* d_in, const int* in_sizes, int n_in,
                              void* d_out, int out_size) {
    const float* x    = (const float*)d_in[0];
    const float* w    = (const float*)d_in[1];
    const float* bias = (const float*)d_in[2];
    float* out        = (float*)d_out;

    prep_kernel<<<1, 32>>>(w);

    dim3 grid(NI / 8, T_DIM / TCH);
    conv_kernel<<<grid, 256>>>(x, bias, out);
}

// round 9
// speedup vs baseline: 2.2743x; 1.1311x over previous
#include <cuda_runtime.h>
#include <cstdint>

#define T_DIM 2048
#define NI    4096
#define L     32
#define F     16
#define TCH   128             // t per CTA
#define NCH   4               // channels per CTA
#define WINR  (TCH + 62)      // 190 staged rows per channel
#define XSTR  193             // smem row stride (odd -> conflict-free)

__device__ float g_wh[L * F];  // [k][f], lag-reversed+normalized, tf32-rounded

__device__ __forceinline__ float tf32r(float x) {
    uint32_t u;
    asm("cvt.rna.tf32.f32 %0, %1;" : "=r"(u) : "f"(x));
    return __uint_as_float(u);
}

#define MMA(c0,c1,c2,c3,a0,a1,a2,a3,b0,b1)                              \
    asm("mma.sync.aligned.m16n8k8.row.col.f32.tf32.tf32.f32 "           \
        "{%0,%1,%2,%3}, {%4,%5,%6,%7}, {%8,%9}, {%0,%1,%2,%3};"         \
        : "+f"(c0), "+f"(c1), "+f"(c2), "+f"(c3)                        \
        : "r"(a0), "r"(a1), "r"(a2), "r"(a3), "r"(b0), "r"(b1))

// pos-constraint + l2-normalize + lag-reverse + tf32 round
__global__ void prep_kernel(const float* __restrict__ w) {
    int f = threadIdx.x;
    if (f < F) {
        float col[L];
        float s = 0.f;
#pragma unroll
        for (int j = 0; j < L; j++) {
            float v = fmaxf(w[j * F + f], 0.f);
            col[j] = v;
            s += v * v;
        }
        float inv = rsqrtf(fmaxf(s, 1e-12f));
#pragma unroll
        for (int k = 0; k < L; k++)
            g_wh[k * F + f] = tf32r(col[L - 1 - k] * inv);  // W[k][f] = w_pn[31-k][f]
    }
}

// CTA: 4 warps, warp w owns channel i = ib + w, computes out[t0..t0+127, i, :].
// 2-term split (Ah + Al) x Bh, independent accumulator chains, bias folded
// into h-accumulator init. 128-thread CTAs @ <=102 regs -> 5 CTAs/SM.
__global__ __launch_bounds__(128, 5) void conv_kernel(const float* __restrict__ x,
                                                      const float* __restrict__ bias,
                                                      float* __restrict__ out) {
    __shared__ float sxh[NCH * XSTR];
    __shared__ float sxl[NCH * XSTR];

    const int tid  = threadIdx.x;
    const int w    = tid >> 5;
    const int lane = tid & 31;
    const int g    = lane >> 2;      // groupID
    const int tg   = lane & 3;       // threadID_in_group
    const int ib   = blockIdx.x * NCH;
    const int t0   = blockIdx.y * TCH;

    // ---- stage x window transposed + tf32-split: sxh[i_loc][t_loc] ----
#pragma unroll
    for (int p = 0; p < 6; p++) {
        int idx = tid + p * 128;           // 768 = 4 ch x 192 rows
        int row = idx >> 2;
        int il  = idx & 3;
        int tau = t0 - 63 + row;
        float v = 0.f;
        if (row < WINR && tau >= 0) v = x[(long)tau * NI + ib + il];
        float h = tf32r(v);
        sxh[il * XSTR + row] = h;
        sxl[il * XSTR + row] = v - h;
    }

    // ---- B fragments with permuted filter columns ----
    // ntile0 col c -> f = (c even) ? 2c : 2c-1 ; ntile1 col c -> (c even) ? 2c+2 : 2c+1
    const int fc0 = (g & 1) ? (2 * g - 1) : (2 * g);
    const int fc1 = (g & 1) ? (2 * g + 1) : (2 * g + 2);
    uint32_t bh[4][2][2];
#pragma unroll
    for (int s = 0; s < 4; s++) {
        int k0 = s * 8 + tg;
        bh[s][0][0] = __float_as_uint(g_wh[k0 * F + fc0]);
        bh[s][0][1] = __float_as_uint(g_wh[(k0 + 4) * F + fc0]);
        bh[s][1][0] = __float_as_uint(g_wh[k0 * F + fc1]);
        bh[s][1][1] = __float_as_uint(g_wh[(k0 + 4) * F + fc1]);
    }

    // bias quad for this lane's filters 4tg..4tg+3
    const float4 bq = reinterpret_cast<const float4*>(bias)[tg];

    __syncthreads();

    // rolling A window: W[j] = x-window value at t_loc = mt*16 + (g+2tg) + 8j
    const float* ph = sxh + w * XSTR + g + 2 * tg;
    const float* pl = sxl + w * XSTR + g + 2 * tg;
    float Wh[9], Wl[9];
#pragma unroll
    for (int j = 0; j < 9; j++) { Wh[j] = ph[8 * j]; Wl[j] = pl[8 * j]; }

    float* const obase = out + (long)(ib + w) * F + 4 * tg;

#pragma unroll
    for (int mt = 0; mt < 8; mt++) {
        // h-chain initialized with bias (mma accumulates onto it); l-chain zero
        float h00 = bq.x, h01 = bq.y, h02 = bq.x, h03 = bq.y;
        float h10 = bq.z, h11 = bq.w, h12 = bq.z, h13 = bq.w;
        float l00 = 0.f, l01 = 0.f, l02 = 0.f, l03 = 0.f;
        float l10 = 0.f, l11 = 0.f, l12 = 0.f, l13 = 0.f;

#pragma unroll
        for (int s = 0; s < 4; s++) {
            // Toeplitz: a1 == a2 (A[g+8][k] == A[g][k+4])
            uint32_t ah0 = __float_as_uint(Wh[2 * s]);
            uint32_t ah1 = __float_as_uint(Wh[2 * s + 1]);
            uint32_t ah3 = __float_as_uint(Wh[2 * s + 2]);
            uint32_t al0 = __float_as_uint(Wl[2 * s]);
            uint32_t al1 = __float_as_uint(Wl[2 * s + 1]);
            uint32_t al3 = __float_as_uint(Wl[2 * s + 2]);

            MMA(h00, h01, h02, h03, ah0, ah1, ah1, ah3, bh[s][0][0], bh[s][0][1]);
            MMA(h10, h11, h12, h13, ah0, ah1, ah1, ah3, bh[s][1][0], bh[s][1][1]);
            MMA(l00, l01, l02, l03, al0, al1, al1, al3, bh[s][0][0], bh[s][0][1]);
            MMA(l10, l11, l12, l13, al0, al1, al1, al3, bh[s][1][0], bh[s][1][1]);
        }

        // epilogue: combine chains + relu, one STG.128 per row
        {
            int ta = t0 + mt * 16 + g;
            float4 va;
            va.x = fmaxf(h00 + l00, 0.f);
            va.y = fmaxf(h01 + l01, 0.f);
            va.z = fmaxf(h10 + l10, 0.f);
            va.w = fmaxf(h11 + l11, 0.f);
            *reinterpret_cast<float4*>(obase + (long)ta * (NI * F)) = va;
            float4 vb;
            vb.x = fmaxf(h02 + l02, 0.f);
            vb.y = fmaxf(h03 + l03, 0.f);
            vb.z = fmaxf(h12 + l12, 0.f);
            vb.w = fmaxf(h13 + l13, 0.f);
            *reinterpret_cast<float4*>(obase + (long)(ta + 8) * (NI * F)) = vb;
        }

        // roll window forward by one m-tile (16 t = 2 positions of 8)
        if (mt < 7) {
#pragma unroll
            for (int j = 0; j < 7; j++) { Wh[j] = Wh[j + 2]; Wl[j] = Wl[j + 2]; }
            Wh[7] = ph[(mt + 1) * 16 + 56];
            Wl[7] = pl[(mt + 1) * 16 + 56];
            Wh[8] = ph[(mt + 1) * 16 + 64];
            Wl[8] = pl[(mt + 1) * 16 + 64];
        }
    }
}

extern "C" void kernel_launch(void* const* d_in, const int* in_sizes, int n_in,
                              void* d_out, int out_size) {
    const float* x    = (const float*)d_in[0];
    const float* w    = (const float*)d_in[1];
    const float* bias = (const float*)d_in[2];
    float* out        = (float*)d_out;

    prep_kernel<<<1, 32>>>(w);

    dim3 grid(NI / NCH, T_DIM / TCH);
    conv_kernel<<<grid, 128>>>(x, bias, out);
}

// round 10
// speedup vs baseline: 2.6321x; 1.1573x over previous
#include <cuda_runtime.h>
#include <cstdint>

#define T_DIM 2048
#define NI    4096
#define L     32
#define F     16
#define TCH   128             // t per CTA
#define NCH   4               // channels per CTA
#define WINR  (TCH + 62)      // 190 staged rows per channel
#define XSTR  193             // smem row stride (odd -> conflict-free)

__device__ float g_wh[L * F];  // [k][f], lag-reversed+normalized, tf32-rounded

__device__ __forceinline__ float tf32r(float x) {
    uint32_t u;
    asm("cvt.rna.tf32.f32 %0, %1;" : "=r"(u) : "f"(x));
    return __uint_as_float(u);
}

#define MMA(c0,c1,c2,c3,a0,a1,a2,a3,b0,b1)                              \
    asm("mma.sync.aligned.m16n8k8.row.col.f32.tf32.tf32.f32 "           \
        "{%0,%1,%2,%3}, {%4,%5,%6,%7}, {%8,%9}, {%0,%1,%2,%3};"         \
        : "+f"(c0), "+f"(c1), "+f"(c2), "+f"(c3)                        \
        : "r"(a0), "r"(a1), "r"(a2), "r"(a3), "r"(b0), "r"(b1))

// pos-constraint + l2-normalize + lag-reverse + tf32 round
__global__ void prep_kernel(const float* __restrict__ w) {
    int f = threadIdx.x;
    if (f < F) {
        float col[L];
        float s = 0.f;
#pragma unroll
        for (int j = 0; j < L; j++) {
            float v = fmaxf(w[j * F + f], 0.f);
            col[j] = v;
            s += v * v;
        }
        float inv = rsqrtf(fmaxf(s, 1e-12f));
#pragma unroll
        for (int k = 0; k < L; k++)
            g_wh[k * F + f] = tf32r(col[L - 1 - k] * inv);  // W[k][f] = w_pn[31-k][f]
    }
}

// CTA: 4 warps, warp w owns channel i = ib + w, computes out[t0..t0+127, i, :].
// Pure tf32 (A and B rounded). Bias folded into accumulator init. B columns
// permuted so each lane's 4 C-values per row are contiguous filters (STG.128).
__global__ __launch_bounds__(128, 8) void conv_kernel(const float* __restrict__ x,
                                                      const float* __restrict__ bias,
                                                      float* __restrict__ out) {
    __shared__ float sxh[NCH * XSTR];

    const int tid  = threadIdx.x;
    const int w    = tid >> 5;
    const int lane = tid & 31;
    const int g    = lane >> 2;      // groupID
    const int tg   = lane & 3;       // threadID_in_group
    const int ib   = blockIdx.x * NCH;
    const int t0   = blockIdx.y * TCH;

    // ---- stage x window transposed + tf32-rounded: sxh[i_loc][t_loc] ----
#pragma unroll
    for (int p = 0; p < 6; p++) {
        int idx = tid + p * 128;           // 768 = 4 ch x 192 rows
        int row = idx >> 2;
        int il  = idx & 3;
        int tau = t0 - 63 + row;
        float v = 0.f;
        if (row < WINR && tau >= 0) v = x[(long)tau * NI + ib + il];
        sxh[il * XSTR + row] = tf32r(v);
    }

    // ---- B fragments with permuted filter columns ----
    // ntile0 col c -> f = (c even) ? 2c : 2c-1 ; ntile1 col c -> (c even) ? 2c+2 : 2c+1
    const int fc0 = (g & 1) ? (2 * g - 1) : (2 * g);
    const int fc1 = (g & 1) ? (2 * g + 1) : (2 * g + 2);
    uint32_t bh[4][2][2];
#pragma unroll
    for (int s = 0; s < 4; s++) {
        int k0 = s * 8 + tg;
        bh[s][0][0] = __float_as_uint(g_wh[k0 * F + fc0]);
        bh[s][0][1] = __float_as_uint(g_wh[(k0 + 4) * F + fc0]);
        bh[s][1][0] = __float_as_uint(g_wh[k0 * F + fc1]);
        bh[s][1][1] = __float_as_uint(g_wh[(k0 + 4) * F + fc1]);
    }

    // bias quad for this lane's filters 4tg..4tg+3
    const float4 bq = reinterpret_cast<const float4*>(bias)[tg];

    __syncthreads();

    // rolling A window: W[j] = x-window value at t_loc = mt*16 + (g+2tg) + 8j
    const float* ph = sxh + w * XSTR + g + 2 * tg;
    float Wh[9];
#pragma unroll
    for (int j = 0; j < 9; j++) Wh[j] = ph[8 * j];

    // incremental store pointers (advance by 16 t-rows per mt)
    float* pa = out + (long)(t0 + g) * (NI * F) + (ib + w) * F + 4 * tg;
    float* pb = pa + (long)8 * (NI * F);
    const long mstride = (long)16 * (NI * F);

#pragma unroll
    for (int mt = 0; mt < 8; mt++) {
        // accumulators initialized with bias
        float h00 = bq.x, h01 = bq.y, h02 = bq.x, h03 = bq.y;
        float h10 = bq.z, h11 = bq.w, h12 = bq.z, h13 = bq.w;

#pragma unroll
        for (int s = 0; s < 4; s++) {
            // Toeplitz: a1 == a2 (A[g+8][k] == A[g][k+4])
            uint32_t ah0 = __float_as_uint(Wh[2 * s]);
            uint32_t ah1 = __float_as_uint(Wh[2 * s + 1]);
            uint32_t ah3 = __float_as_uint(Wh[2 * s + 2]);

            MMA(h00, h01, h02, h03, ah0, ah1, ah1, ah3, bh[s][0][0], bh[s][0][1]);
            MMA(h10, h11, h12, h13, ah0, ah1, ah1, ah3, bh[s][1][0], bh[s][1][1]);
        }

        // epilogue: relu, one STG.128 per row
        {
            float4 va;
            va.x = fmaxf(h00, 0.f);
            va.y = fmaxf(h01, 0.f);
            va.z = fmaxf(h10, 0.f);
            va.w = fmaxf(h11, 0.f);
            *reinterpret_cast<float4*>(pa) = va;
            float4 vb;
            vb.x = fmaxf(h02, 0.f);
            vb.y = fmaxf(h03, 0.f);
            vb.z = fmaxf(h12, 0.f);
            vb.w = fmaxf(h13, 0.f);
            *reinterpret_cast<float4*>(pb) = vb;
            pa += mstride;
            pb += mstride;
        }

        // roll window forward by one m-tile (16 t = 2 positions of 8)
        if (mt < 7) {
#pragma unroll
            for (int j = 0; j < 7; j++) Wh[j] = Wh[j + 2];
            Wh[7] = ph[(mt + 1) * 16 + 56];
            Wh[8] = ph[(mt + 1) * 16 + 64];
        }
    }
}

extern "C" void kernel_launch(void* const* d_in, const int* in_sizes, int n_in,
                              void* d_out, int out_size) {
    const float* x    = (const float*)d_in[0];
    const float* w    = (const float*)d_in[1];
    const float* bias = (const float*)d_in[2];
    float* out        = (float*)d_out;

    prep_kernel<<<1, 32>>>(w);

    dim3 grid(NI / NCH, T_DIM / TCH);
    conv_kernel<<<grid, 128>>>(x, bias, out);
}

// round 11
// speedup vs baseline: 2.7940x; 1.0615x over previous
#include <cuda_runtime.h>
#include <cstdint>

#define T_DIM 2048
#define NI    4096
#define L     32
#define F     16
#define TCH   256             // t per CTA
#define NCH   4               // channels per CTA
#define WINR  (TCH + 62)      // 318 staged rows per channel
#define XSTR  321             // smem row stride (odd -> conflict-free)
#define NMT   (TCH / 16)      // 16 m-tiles

__device__ float g_wh[L * F];  // [k][f], lag-reversed+normalized, tf32-rounded

__device__ __forceinline__ float tf32r(float x) {
    uint32_t u;
    asm("cvt.rna.tf32.f32 %0, %1;" : "=r"(u) : "f"(x));
    return __uint_as_float(u);
}

#define MMA(c0,c1,c2,c3,a0,a1,a2,a3,b0,b1)                              \
    asm("mma.sync.aligned.m16n8k8.row.col.f32.tf32.tf32.f32 "           \
        "{%0,%1,%2,%3}, {%4,%5,%6,%7}, {%8,%9}, {%0,%1,%2,%3};"         \
        : "+f"(c0), "+f"(c1), "+f"(c2), "+f"(c3)                        \
        : "r"(a0), "r"(a1), "r"(a2), "r"(a3), "r"(b0), "r"(b1))

// pos-constraint + l2-normalize + lag-reverse + tf32 round
__global__ void prep_kernel(const float* __restrict__ w) {
    int f = threadIdx.x;
    if (f < F) {
        float col[L];
        float s = 0.f;
#pragma unroll
        for (int j = 0; j < L; j++) {
            float v = fmaxf(w[j * F + f], 0.f);
            col[j] = v;
            s += v * v;
        }
        float inv = rsqrtf(fmaxf(s, 1e-12f));
#pragma unroll
        for (int k = 0; k < L; k++)
            g_wh[k * F + f] = tf32r(col[L - 1 - k] * inv);  // W[k][f] = w_pn[31-k][f]
    }
}

// CTA: 4 warps, warp w owns channel i = ib + w, computes out[t0..t0+255, i, :].
// Pure tf32. Bias folded into accumulator init. B columns permuted so each
// lane's 4 C-values per row are contiguous filters (one STG.128 per row).
__global__ __launch_bounds__(128, 8) void conv_kernel(const float* __restrict__ x,
                                                      const float* __restrict__ bias,
                                                      float* __restrict__ out) {
    __shared__ float sxh[NCH * XSTR];

    const int tid  = threadIdx.x;
    const int w    = tid >> 5;
    const int lane = tid & 31;
    const int g    = lane >> 2;      // groupID
    const int tg   = lane & 3;       // threadID_in_group
    const int ib   = blockIdx.x * NCH;
    const int t0   = blockIdx.y * TCH;

    // ---- stage x window transposed + tf32-rounded: sxh[i_loc][t_loc] ----
    if (t0 >= 63) {                   // interior: no boundary guard needed
#pragma unroll
        for (int p = 0; p < 10; p++) {
            int idx = tid + p * 128;            // 1272 = 4 ch x 318 rows
            if (idx < NCH * WINR) {
                int row = idx >> 2;
                int il  = idx & 3;
                sxh[il * XSTR + row] = tf32r(x[(long)(t0 - 63 + row) * NI + ib + il]);
            }
        }
    } else {                          // first t-block: zero-fill t<0
#pragma unroll
        for (int p = 0; p < 10; p++) {
            int idx = tid + p * 128;
            if (idx < NCH * WINR) {
                int row = idx >> 2;
                int il  = idx & 3;
                int tau = t0 - 63 + row;
                float v = (tau >= 0) ? x[(long)tau * NI + ib + il] : 0.f;
                sxh[il * XSTR + row] = tf32r(v);
            }
        }
    }

    // ---- B fragments with permuted filter columns ----
    // ntile0 col c -> f = (c even) ? 2c : 2c-1 ; ntile1 col c -> (c even) ? 2c+2 : 2c+1
    const int fc0 = (g & 1) ? (2 * g - 1) : (2 * g);
    const int fc1 = (g & 1) ? (2 * g + 1) : (2 * g + 2);
    uint32_t bh[4][2][2];
#pragma unroll
    for (int s = 0; s < 4; s++) {
        int k0 = s * 8 + tg;
        bh[s][0][0] = __float_as_uint(g_wh[k0 * F + fc0]);
        bh[s][0][1] = __float_as_uint(g_wh[(k0 + 4) * F + fc0]);
        bh[s][1][0] = __float_as_uint(g_wh[k0 * F + fc1]);
        bh[s][1][1] = __float_as_uint(g_wh[(k0 + 4) * F + fc1]);
    }

    // bias quad for this lane's filters 4tg..4tg+3
    const float4 bq = reinterpret_cast<const float4*>(bias)[tg];

    __syncthreads();

    // rolling A window: W[j] = x-window value at t_loc = mt*16 + (g+2tg) + 8j
    const float* ph = sxh + w * XSTR + g + 2 * tg;
    float Wh[9];
#pragma unroll
    for (int j = 0; j < 9; j++) Wh[j] = ph[8 * j];

    // incremental store pointers (advance by 16 t-rows per mt)
    float* pa = out + (long)(t0 + g) * (NI * F) + (ib + w) * F + 4 * tg;
    float* pb = pa + (long)8 * (NI * F);
    const long mstride = (long)16 * (NI * F);

#pragma unroll
    for (int mt = 0; mt < NMT; mt++) {
        // accumulators initialized with bias
        float h00 = bq.x, h01 = bq.y, h02 = bq.x, h03 = bq.y;
        float h10 = bq.z, h11 = bq.w, h12 = bq.z, h13 = bq.w;

#pragma unroll
        for (int s = 0; s < 4; s++) {
            // Toeplitz: a1 == a2 (A[g+8][k] == A[g][k+4])
            uint32_t ah0 = __float_as_uint(Wh[2 * s]);
            uint32_t ah1 = __float_as_uint(Wh[2 * s + 1]);
            uint32_t ah3 = __float_as_uint(Wh[2 * s + 2]);

            MMA(h00, h01, h02, h03, ah0, ah1, ah1, ah3, bh[s][0][0], bh[s][0][1]);
            MMA(h10, h11, h12, h13, ah0, ah1, ah1, ah3, bh[s][1][0], bh[s][1][1]);
        }

        // epilogue: relu, one STG.128 per row
        {
            float4 va;
            va.x = fmaxf(h00, 0.f);
            va.y = fmaxf(h01, 0.f);
            va.z = fmaxf(h10, 0.f);
            va.w = fmaxf(h11, 0.f);
            *reinterpret_cast<float4*>(pa) = va;
            float4 vb;
            vb.x = fmaxf(h02, 0.f);
            vb.y = fmaxf(h03, 0.f);
            vb.z = fmaxf(h12, 0.f);
            vb.w = fmaxf(h13, 0.f);
            *reinterpret_cast<float4*>(pb) = vb;
            pa += mstride;
            pb += mstride;
        }

        // roll window forward by one m-tile (16 t = 2 positions of 8)
        if (mt < NMT - 1) {
#pragma unroll
            for (int j = 0; j < 7; j++) Wh[j] = Wh[j + 2];
            Wh[7] = ph[(mt + 1) * 16 + 56];
            Wh[8] = ph[(mt + 1) * 16 + 64];
        }
    }
}

extern "C" void kernel_launch(void* const* d_in, const int* in_sizes, int n_in,
                              void* d_out, int out_size) {
    const float* x    = (const float*)d_in[0];
    const float* w    = (const float*)d_in[1];
    const float* bias = (const float*)d_in[2];
    float* out        = (float*)d_out;

    prep_kernel<<<1, 32>>>(w);

    dim3 grid(NI / NCH, T_DIM / TCH);
    conv_kernel<<<grid, 128>>>(x, bias, out);
}